// round 2
// baseline (speedup 1.0000x reference)
#include <cuda_runtime.h>
#include <cuda_fp16.h>
#include <cstdint>

// ----------------------------------------------------------------------------
// diff_attention: B=8, S=2048, D=1024
//
// Math simplifications (proved from the reference):
//  * Q1/K1 rows are identical per batch (X1 broadcast) -> A1 constant over
//    (q,k) -> softmax(A1) == 1/S exactly ->
//      output = softmax(A2) @ V - (alpha/S) * sum_k V[b,k,:]
//    (Wq1,bq1,Wk1,bk1 are dead inputs)
//  * V = vconst[b] + X2 @ Wv[D:], vconst[b] = X1[b] @ Wv[:D] + bv
//
// Pipeline (fp16 MMA, fp32 accumulate, cp.async double-buffered GEMMs):
//  1. convert X2, Wq2, Wk2, Wv[D:] to half; vconst (fp32, tiny)
//  2. GEMM: Qh/Kh/Vh = Xh @ W + bias            [8x2048,1024]x[1024,1024]
//  3. corr[b][d] = -(alpha/S) * sum_s Vh[b][s][d]
//  4. GEMM: logits = (Qh @ Kh^T) * (1/32)  (fp32 out, per batch)
//  5. softmax rows -> P (half)
//  6. GEMM: out = P @ Vh + corr (fp32 out)
// ----------------------------------------------------------------------------

#define DEVINL __device__ __forceinline__

static constexpr int B = 8;
static constexpr int S = 2048;
static constexpr int D = 1024;

// ---------------- device scratch (no cudaMalloc allowed) --------------------
__device__ __half g_Xh[B * S * D];          // 32 MB
__device__ __half g_Wh[3 * D * D];          //  6 MB  (Wq2, Wk2, Wv_bottom) [k][n]
__device__ __half g_Qh[B * S * D];          // 32 MB
__device__ __half g_Kh[B * S * D];          // 32 MB
__device__ __half g_Vh[B * S * D];          // 32 MB
__device__ float  g_vconst[B * D];          // X1@Wv_top + bv
__device__ float  g_corr[B * D];            // -(alpha/S) * colsum(V)
__device__ float  g_logits[B * S * S];      // 128 MB
__device__ __half g_P[B * S * S];           //  64 MB

// ---------------- small helpers ---------------------------------------------
DEVINL uint32_t smem_u32(const void* p) {
    return (uint32_t)__cvta_generic_to_shared(p);
}
DEVINL void ldm_x4(uint32_t& r0, uint32_t& r1, uint32_t& r2, uint32_t& r3, uint32_t a) {
    asm volatile("ldmatrix.sync.aligned.m8n8.x4.shared.b16 {%0,%1,%2,%3},[%4];\n"
                 : "=r"(r0), "=r"(r1), "=r"(r2), "=r"(r3) : "r"(a));
}
DEVINL void ldm_x2(uint32_t& r0, uint32_t& r1, uint32_t a) {
    asm volatile("ldmatrix.sync.aligned.m8n8.x2.shared.b16 {%0,%1},[%2];\n"
                 : "=r"(r0), "=r"(r1) : "r"(a));
}
DEVINL void ldm_x2t(uint32_t& r0, uint32_t& r1, uint32_t a) {
    asm volatile("ldmatrix.sync.aligned.m8n8.x2.trans.shared.b16 {%0,%1},[%2];\n"
                 : "=r"(r0), "=r"(r1) : "r"(a));
}
DEVINL void mma16816(float c[4], uint32_t a0, uint32_t a1, uint32_t a2, uint32_t a3,
                     uint32_t b0, uint32_t b1) {
    asm volatile(
        "mma.sync.aligned.m16n8k16.row.col.f32.f16.f16.f32 "
        "{%0,%1,%2,%3},{%4,%5,%6,%7},{%8,%9},{%0,%1,%2,%3};\n"
        : "+f"(c[0]), "+f"(c[1]), "+f"(c[2]), "+f"(c[3])
        : "r"(a0), "r"(a1), "r"(a2), "r"(a3), "r"(b0), "r"(b1));
}
DEVINL void cpasync16(void* sdst, const void* gsrc) {
    asm volatile("cp.async.cg.shared.global [%0], [%1], 16;\n"
                 :: "r"(smem_u32(sdst)), "l"(gsrc));
}
DEVINL void cpcommit() { asm volatile("cp.async.commit_group;\n" ::: "memory"); }
template <int N> DEVINL void cpwait() {
    asm volatile("cp.async.wait_group %0;\n" :: "n"(N) : "memory");
}

// ---------------- conversion / small kernels --------------------------------
__global__ void f2h_kernel(const float* __restrict__ x, __half* __restrict__ y, int n) {
    int i = blockIdx.x * blockDim.x + threadIdx.x;
    int stride = gridDim.x * blockDim.x;
    for (; i < n; i += stride) y[i] = __float2half(x[i]);
}

// vconst[b][n] = sum_k X1[b][k] * Wv[k][n] + bv[n]   (Wv top rows 0..D-1)
__global__ void vconst_kernel(const float* __restrict__ X1, const float* __restrict__ Wv,
                              const float* __restrict__ bv, float* __restrict__ vc) {
    int n = blockIdx.x * blockDim.x + threadIdx.x;   // 0..D-1
    int b = blockIdx.y;
    float acc = bv[n];
    const float* x = X1 + b * D;
    for (int k = 0; k < D; k++) acc += x[k] * Wv[(long)k * D + n];
    vc[b * D + n] = acc;
}

// corr[b][d] = -(alpha/S) * sum_s Vh[b][s][d]
__global__ void corr_kernel(const __half* __restrict__ Vh, const float* __restrict__ alpha,
                            float* __restrict__ corr) {
    int d = blockIdx.x * blockDim.x + threadIdx.x;
    int b = blockIdx.y;
    float s = 0.f;
    const __half* v = Vh + (long)b * S * D + d;
    for (int i = 0; i < S; i++) s += __half2float(v[(long)i * D]);
    corr[b * D + d] = -(*alpha) * (1.0f / (float)S) * s;
}

// row softmax over 2048 fp32 logits -> half probabilities
__global__ void softmax_kernel(const float* __restrict__ L, __half* __restrict__ P) {
    const long row = blockIdx.x;
    const float* x = L + row * (long)S;
    __half* p = P + row * (long)S;
    const int tid = threadIdx.x;

    float v[8];
    float mx = -1e30f;
#pragma unroll
    for (int i = 0; i < 8; i++) { v[i] = x[tid + i * 256]; mx = fmaxf(mx, v[i]); }
#pragma unroll
    for (int o = 16; o; o >>= 1) mx = fmaxf(mx, __shfl_xor_sync(0xffffffffu, mx, o));
    __shared__ float redm[8];
    if ((tid & 31) == 0) redm[tid >> 5] = mx;
    __syncthreads();
    float m2 = redm[0];
#pragma unroll
    for (int i = 1; i < 8; i++) m2 = fmaxf(m2, redm[i]);

    float s = 0.f;
#pragma unroll
    for (int i = 0; i < 8; i++) { v[i] = __expf(v[i] - m2); s += v[i]; }
#pragma unroll
    for (int o = 16; o; o >>= 1) s += __shfl_xor_sync(0xffffffffu, s, o);
    __shared__ float reds[8];
    if ((tid & 31) == 0) reds[tid >> 5] = s;
    __syncthreads();
    float st = 0.f;
#pragma unroll
    for (int i = 0; i < 8; i++) st += reds[i];
    float inv = 1.0f / st;
#pragma unroll
    for (int i = 0; i < 8; i++) p[tid + i * 256] = __float2half(v[i] * inv);
}

// ---------------- the workhorse GEMM (2-stage cp.async pipeline) -------------
// C[z][M=2048][N] = A[z][M][K] * B'   (+ bias, * scale)
// B_KN=true : B stored [K][N] row-major (ldmatrix.trans)
// B_KN=false: B stored [N][K] row-major (TN gemm)
// All dims are multiples of tile sizes -> no bounds checks.
template <bool B_KN, bool OUT_HALF>
__launch_bounds__(256)
__global__ void gemm_tc(const __half* __restrict__ A, const __half* __restrict__ Bm,
                        void* __restrict__ Cv,
                        int N, int K, int lda, int ldb, int ldc,
                        long sAz, long sBz, long sCz,
                        const float* __restrict__ bias, int biasStrideZ, float scale) {
    constexpr int BMt = 128, BNt = 128, BKt = 32;
    const int z = blockIdx.z;
    A += (long)z * sAz;
    Bm += (long)z * sBz;
    const int m0 = blockIdx.y * BMt, n0 = blockIdx.x * BNt;

    __shared__ __half As[2][BMt][BKt + 8];
    constexpr int BROWS = B_KN ? BKt : BNt;
    constexpr int BCOLS = B_KN ? (BNt + 8) : (BKt + 8);
    __shared__ __half Bs[2][BROWS][BCOLS];

    const int tid = threadIdx.x;
    const int lane = tid & 31, warp = tid >> 5;
    const int wm = (warp & 3) * 32;   // 4 warps along M -> 128
    const int wn = (warp >> 2) * 64;  // 2 warps along N -> 128

    // per-thread load coordinates (8 chunks of 16B total per tile pair)
    const int ar0 = tid >> 2, akc = (tid & 3) * 8;           // A: 128 rows x 4 chunks
    const int ar1 = (tid + 256) >> 2;
    int br0, bc0, br1, bc1;
    if (B_KN) {
        br0 = tid >> 4; bc0 = (tid & 15) * 8;                // 32 rows x 16 chunks
        br1 = (tid + 256) >> 4; bc1 = bc0;
    } else {
        br0 = tid >> 2; bc0 = (tid & 3) * 8;                 // 128 rows x 4 chunks
        br1 = (tid + 256) >> 2; bc1 = bc0;
    }

    auto load_tile = [&](int k0, int buf) {
        cpasync16(&As[buf][ar0][akc], &A[(long)(m0 + ar0) * lda + k0 + akc]);
        cpasync16(&As[buf][ar1][akc], &A[(long)(m0 + ar1) * lda + k0 + akc]);
        if (B_KN) {
            cpasync16(&Bs[buf][br0][bc0], &Bm[(long)(k0 + br0) * ldb + n0 + bc0]);
            cpasync16(&Bs[buf][br1][bc1], &Bm[(long)(k0 + br1) * ldb + n0 + bc1]);
        } else {
            cpasync16(&Bs[buf][br0][bc0], &Bm[(long)(n0 + br0) * ldb + k0 + bc0]);
            cpasync16(&Bs[buf][br1][bc1], &Bm[(long)(n0 + br1) * ldb + k0 + bc1]);
        }
        cpcommit();
    };

    float c[2][8][4];
#pragma unroll
    for (int mt = 0; mt < 2; mt++)
#pragma unroll
        for (int nt = 0; nt < 8; nt++)
#pragma unroll
            for (int i = 0; i < 4; i++) c[mt][nt][i] = 0.f;

    const int T = K / BKt;
    load_tile(0, 0);

    for (int kt = 0; kt < T; kt++) {
        if (kt + 1 < T) {
            load_tile((kt + 1) * BKt, (kt + 1) & 1);
            cpwait<1>();
        } else {
            cpwait<0>();
        }
        __syncthreads();

        const int buf = kt & 1;
#pragma unroll
        for (int kk = 0; kk < 2; kk++) {
            uint32_t a[2][4];
#pragma unroll
            for (int mt = 0; mt < 2; mt++) {
                uint32_t addr = smem_u32(
                    &As[buf][wm + mt * 16 + (lane & 15)][kk * 16 + (lane >> 4) * 8]);
                ldm_x4(a[mt][0], a[mt][1], a[mt][2], a[mt][3], addr);
            }
            uint32_t bfr[8][2];
#pragma unroll
            for (int nt = 0; nt < 8; nt++) {
                if (B_KN) {
                    uint32_t addr = smem_u32(&Bs[buf][kk * 16 + (lane & 15)][wn + nt * 8]);
                    ldm_x2t(bfr[nt][0], bfr[nt][1], addr);
                } else {
                    uint32_t addr = smem_u32(
                        &Bs[buf][wn + nt * 8 + (lane & 7)][kk * 16 + ((lane >> 3) & 1) * 8]);
                    ldm_x2(bfr[nt][0], bfr[nt][1], addr);
                }
            }
#pragma unroll
            for (int mt = 0; mt < 2; mt++)
#pragma unroll
                for (int nt = 0; nt < 8; nt++)
                    mma16816(c[mt][nt], a[mt][0], a[mt][1], a[mt][2], a[mt][3],
                             bfr[nt][0], bfr[nt][1]);
        }
        __syncthreads();
    }

    // --- epilogue ---
    const int g = lane >> 2, t4 = lane & 3;
#pragma unroll
    for (int mt = 0; mt < 2; mt++) {
#pragma unroll
        for (int nt = 0; nt < 8; nt++) {
            int col = n0 + wn + nt * 8 + t4 * 2;
            float b0 = 0.f, b1 = 0.f;
            if (bias) {
                b0 = bias[z * biasStrideZ + col];
                b1 = bias[z * biasStrideZ + col + 1];
            }
#pragma unroll
            for (int h = 0; h < 2; h++) {
                int row = m0 + wm + mt * 16 + g + h * 8;
                float v0 = c[mt][nt][h * 2 + 0] * scale + b0;
                float v1 = c[mt][nt][h * 2 + 1] * scale + b1;
                long off = (long)z * sCz + (long)row * ldc + col;
                if (OUT_HALF) {
                    *(__half2*)((__half*)Cv + off) = __floats2half2_rn(v0, v1);
                } else {
                    *(float2*)((float*)Cv + off) = make_float2(v0, v1);
                }
            }
        }
    }
}

// ---------------- launch ------------------------------------------------------
extern "C" void kernel_launch(void* const* d_in, const int* in_sizes, int n_in,
                              void* d_out, int out_size) {
    const float* X1 = (const float*)d_in[0];
    const float* X2 = (const float*)d_in[1];
    // d_in[2],[3],[6],[7] (Wq1,bq1,Wk1,bk1) are provably dead
    const float* Wq2 = (const float*)d_in[4];
    const float* bq2 = (const float*)d_in[5];
    const float* Wk2 = (const float*)d_in[8];
    const float* bk2 = (const float*)d_in[9];
    const float* Wv = (const float*)d_in[10];
    const float* bv = (const float*)d_in[11];
    const float* alpha = (const float*)d_in[12];
    float* out = (float*)d_out;

    __half *Xh, *Wh, *Qh, *Kh, *Vh, *P;
    float *vconst, *corr, *logits;
    cudaGetSymbolAddress((void**)&Xh, g_Xh);
    cudaGetSymbolAddress((void**)&Wh, g_Wh);
    cudaGetSymbolAddress((void**)&Qh, g_Qh);
    cudaGetSymbolAddress((void**)&Kh, g_Kh);
    cudaGetSymbolAddress((void**)&Vh, g_Vh);
    cudaGetSymbolAddress((void**)&P, g_P);
    cudaGetSymbolAddress((void**)&vconst, g_vconst);
    cudaGetSymbolAddress((void**)&corr, g_corr);
    cudaGetSymbolAddress((void**)&logits, g_logits);

    const int NX = B * S * D;   // 16,777,216
    const int NW = D * D;       //  1,048,576

    // 1. conversions + vconst
    f2h_kernel<<<4096, 256>>>(X2, Xh, NX);
    f2h_kernel<<<1024, 256>>>(Wq2, Wh + 0 * NW, NW);
    f2h_kernel<<<1024, 256>>>(Wk2, Wh + 1 * NW, NW);
    f2h_kernel<<<1024, 256>>>(Wv + (long)D * D, Wh + 2 * NW, NW);  // bottom rows
    vconst_kernel<<<dim3(4, B), 256>>>(X1, Wv, bv, vconst);

    // 2. Q/K/V projections: [z=8][2048,1024] = Xh[z] @ W (+bias)
    {
        dim3 grid(D / 128, S / 128, B);
        gemm_tc<true, true><<<grid, 256>>>(Xh, Wh + 0 * NW, Qh, D, D, D, D, D,
                                           (long)S * D, 0, (long)S * D, bq2, 0, 1.0f);
        gemm_tc<true, true><<<grid, 256>>>(Xh, Wh + 1 * NW, Kh, D, D, D, D, D,
                                           (long)S * D, 0, (long)S * D, bk2, 0, 1.0f);
        gemm_tc<true, true><<<grid, 256>>>(Xh, Wh + 2 * NW, Vh, D, D, D, D, D,
                                           (long)S * D, 0, (long)S * D, vconst, D, 1.0f);
    }

    // 3. correction term from V
    corr_kernel<<<dim3(4, B), 256>>>(Vh, alpha, corr);

    // 4. logits = (Q @ K^T) / 32
    {
        dim3 grid(S / 128, S / 128, B);
        gemm_tc<false, false><<<grid, 256>>>(Qh, Kh, logits, S, D, D, D, S,
                                             (long)S * D, (long)S * D, (long)S * S,
                                             nullptr, 0, 0.03125f);
    }

    // 5. softmax rows -> P
    softmax_kernel<<<B * S, 256>>>(logits, P);

    // 6. out = P @ V + corr
    {
        dim3 grid(D / 128, S / 128, B);
        gemm_tc<true, false><<<grid, 256>>>(P, Vh, out, D, S, S, D, D,
                                            (long)S * S, (long)S * D, (long)S * D,
                                            corr, D, 1.0f);
    }
}